// round 15
// baseline (speedup 1.0000x reference)
#include <cuda_runtime.h>
#include <stdint.h>

#define JAX_PARTITIONABLE 1

#define BSZ   2
#define CH    64
#define FLATN 16384
#define NPTS  2048
#define KSMP  256
#define HID   32
#define PT    8
#define TW    8                       // points per pairW block
#define GXIB  (BSZ*NPTS/PT)          // 512 gxifeat blocks
#define DENB  (FLATN/64*BSZ)         // 512 dense blocks
#define GUMB  (BSZ*KSMP)             // 512 gumbel-table blocks

typedef unsigned long long u64;

// ---------------- device scratch ------------------------------------------
__device__ float g_xi    [BSZ*NPTS*CH];
__device__ float g_mpe   [BSZ*NPTS*CH];
__device__ float g_A1    [BSZ*NPTS*HID];
__device__ float g_prob  [BSZ*NPTS];
__device__ float g_logp  [BSZ*NPTS];
__device__ float g_B1T   [BSZ*HID*KSMP];     // [b][i][k], bias1 folded in
__device__ float2 g_tfP  [BSZ*KSMP*CH];      // interleaved {tf@W_I, tf@W_E}
__device__ float2 g_wiwe [BSZ*NPTS*KSMP];    // per-(n,k) {wi, we}
__device__ float g_nek   [BSZ*KSMP];
__device__ float g_gum   [BSZ*KSMP*NPTS];    // gumbel noise table [bi][n]
__device__ float g_ctx   [BSZ*NPTS*CH];      // projected ctx (dense, coalesced)
__device__ float g_Weff  [4*CH*CH];          // w_r1 @ w_r2
__device__ float g_beff  [CH];
__device__ float g_s1[HID], g_bias1[HID], g_W2T[HID*HID], g_bias2[HID];
__device__ float g_sne[HID], g_biasne[HID];

// ---------------- helpers ---------------------------------------------------
__device__ __forceinline__ float warpsum(float v) {
    #pragma unroll
    for (int o = 16; o > 0; o >>= 1) v += __shfl_xor_sync(0xffffffffu, v, o);
    return v;
}
__device__ __forceinline__ u64 pack2(float lo, float hi) {
    u64 r; asm("mov.b64 %0, {%1,%2};" : "=l"(r) : "f"(lo), "f"(hi)); return r;
}
__device__ __forceinline__ void unpack2(u64 v, float& lo, float& hi) {
    asm("mov.b64 {%0,%1}, %2;" : "=f"(lo), "=f"(hi) : "l"(v));
}
__device__ __forceinline__ u64 fma2(u64 a, u64 b, u64 c) {
    u64 d; asm("fma.rn.f32x2 %0, %1, %2, %3;" : "=l"(d) : "l"(a), "l"(b), "l"(c)); return d;
}
__device__ __forceinline__ uint32_t rotl32(uint32_t x, int d) {
    return (x << d) | (x >> (32 - d));
}
__device__ __forceinline__ void tf2x32(uint32_t k0, uint32_t k1,
                                       uint32_t x0, uint32_t x1,
                                       uint32_t& o0, uint32_t& o1) {
    uint32_t ks0 = k0, ks1 = k1, ks2 = k0 ^ k1 ^ 0x1BD11BDAu;
    x0 += ks0; x1 += ks1;
#define TF_RND(r) { x0 += x1; x1 = rotl32(x1, r); x1 ^= x0; }
    TF_RND(13) TF_RND(15) TF_RND(26) TF_RND(6)  x0 += ks1; x1 += ks2 + 1u;
    TF_RND(17) TF_RND(29) TF_RND(16) TF_RND(24) x0 += ks2; x1 += ks0 + 2u;
    TF_RND(13) TF_RND(15) TF_RND(26) TF_RND(6)  x0 += ks0; x1 += ks1 + 3u;
    TF_RND(17) TF_RND(29) TF_RND(16) TF_RND(24) x0 += ks1; x1 += ks2 + 4u;
    TF_RND(13) TF_RND(15) TF_RND(26) TF_RND(6)  x0 += ks2; x1 += ks0 + 5u;
#undef TF_RND
    o0 = x0; o1 = x1;
}
__device__ __forceinline__ void batch_keys(int b, uint32_t& kb0, uint32_t& kb1) {
#if JAX_PARTITIONABLE
    tf2x32(0u, 42u, 0u, (uint32_t)b, kb0, kb1);
#else
    uint32_t a0, a1, c0, c1;
    tf2x32(0u, 42u, 0u, 2u, a0, a1);
    tf2x32(0u, 42u, 1u, 3u, c0, c1);
    if (b == 0) { kb0 = a0; kb1 = c0; } else { kb0 = a1; kb1 = c1; }
#endif
}
__device__ __forceinline__ float gumbel_of(uint32_t kb0, uint32_t kb1, uint32_t m) {
    uint32_t o0, o1, bits;
#if JAX_PARTITIONABLE
    tf2x32(kb0, kb1, 0u, m, o0, o1);
    bits = o0 ^ o1;
#else
    const uint32_t half = (KSMP * NPTS) / 2;
    if (m < half) { tf2x32(kb0, kb1, m, m + half, o0, o1); bits = o0; }
    else          { tf2x32(kb0, kb1, m - half, m, o0, o1); bits = o1; }
#endif
    const float TINY = 1.1754943508222875e-38f;
    float f = __uint_as_float((bits >> 9) | 0x3f800000u) - 1.0f;
    float u = fmaxf(f + TINY, TINY);
    return -logf(-logf(u));
}

// ---------------- weff + prep (fused) ---------------------------------------
__global__ void weffprep_kernel(const float* w_r1, const float* w_r2,
                                const float* b_ne1, const float* g_ne, const float* be_ne,
                                const float* b_p1,  const float* g_p1, const float* be_p1,
                                const float* w_p2,  const float* b_p2, const float* g_p2,
                                const float* be_p2, const float* b_r1, const float* b_r2) {
    __shared__ float row[2*CH];
    int c = blockIdx.x, f = threadIdx.x;
    row[f]      = w_r1[c*2*CH + f];
    row[f + CH] = w_r1[c*2*CH + f + CH];
    __syncthreads();
    float acc = 0.f;
    #pragma unroll 8
    for (int m = 0; m < 2*CH; m++) acc = fmaf(row[m], w_r2[m*CH + f], acc);
    g_Weff[c*CH + f] = acc;

    if (blockIdx.x == 0) {
        int t = threadIdx.x;
        float inv = 1.0f / sqrtf(1.0f + 1e-5f);
        if (t < HID) {
            float sne = g_ne[t] * inv;
            g_sne[t] = sne;
            g_biasne[t] = fmaf(b_ne1[t], sne, be_ne[t]);
            float s1 = g_p1[t] * inv;
            g_s1[t] = s1;
            g_bias1[t] = fmaf(b_p1[t], s1, be_p1[t]);
            float s2 = g_p2[t] * inv;
            g_bias2[t] = fmaf(b_p2[t], s2, be_p2[t]);
            for (int i = 0; i < HID; i++)
                g_W2T[t*HID + i] = w_p2[i*HID + t] * s2;
        }
        if (t < CH) {
            float a2 = b_r2[t];
            for (int m = 0; m < 2*CH; m++) a2 = fmaf(b_r1[m], w_r2[m*CH + t], a2);
            g_beff[t] = a2;
        }
    }
}

// ---------------- fused gxifeat + dense + gumbel-table ----------------------
__global__ void __launch_bounds__(256) gxidense_kernel(
        const float* input, const int* mask_idx,
        const float* w_ne1, const float* w_ne2, const float* b_ne2,
        const float* w_p1, float* out) {
    __shared__ float X[CH*65];
    __shared__ __align__(16) float Wl[CH*CH];
    __shared__ float bl[CH];
    int t = threadIdx.x;

    if (blockIdx.x < GXIB) {
        // ---- gxifeat path ----
        float* xs = X;
        __shared__ int   vs[PT];
        __shared__ float divs[HID];
        int b  = blockIdx.x / (NPTS/PT);
        int p0 = (blockIdx.x % (NPTS/PT)) * PT;
        const float kc = -0.1439115683121279f;   // -ln(10000)/64
        if (t < PT) vs[t] = mask_idx[b*NPTS + p0 + t];
        if (t < HID) divs[t] = expf((float)(2*t) * kc);
        __syncthreads();
        for (int idx = t; idx < PT*CH; idx += 256) {
            int p = idx >> 6, c = idx & 63;
            int v = vs[p];
            float ang = (float)v * divs[c >> 1];
            float pe  = (c & 1) ? cosf(ang) : sinf(ang);
            float xi  = input[(b*CH + c)*FLATN + v] + pe;
            int bn = b*NPTS + p0 + p;
            g_xi [bn*CH + c] = xi;
            g_mpe[bn*CH + c] = pe;
            xs[p*CH + c] = xi;
        }
        __syncthreads();
        int w = t >> 5, j = t & 31;
        float dn = 0.f, dp = 0.f;
        #pragma unroll
        for (int c = 0; c < CH; c++) {
            float x = xs[w*CH + c];
            dn = fmaf(x, w_ne1[c*HID + j], dn);
            dp = fmaf(x, w_p1 [c*HID + j], dp);
        }
        int bn = b*NPTS + p0 + w;
        g_A1[bn*HID + j] = dp * g_s1[j];
        float h = fmaxf(fmaf(dn, g_sne[j], g_biasne[j]), 0.f);
        float s = warpsum(h * w_ne2[j]);
        if (j == 0) {
            float logit = s + b_ne2[0];
            float p = 1.f / (1.f + expf(-logit));
            g_prob[bn] = p;
            g_logp[bn] = logf(p);
        }
    } else if (blockIdx.x < GXIB + DENB) {
        // ---- dense path ----
        int d  = blockIdx.x - GXIB;
        int b  = d >> 8;
        int v0 = (d & 255) * 64;
        for (int q = t; q < CH*64; q += 256) {
            int c = q >> 6, vl = q & 63;
            X[c*65 + vl] = input[(b*CH + c)*FLATN + v0 + vl];
        }
        for (int q = t; q < CH*CH; q += 256) Wl[q] = g_Weff[q] + g_Weff[3*CH*CH + q];
        if (t < CH) bl[t] = g_beff[t];
        __syncthreads();

        int vl = t & 63, fb = (t >> 6) * 16;
        u64 acc2[8];
        #pragma unroll
        for (int r = 0; r < 8; r++) acc2[r] = pack2(bl[fb + 2*r], bl[fb + 2*r + 1]);
        for (int c = 0; c < CH; c++) {
            float xv = X[c*65 + vl];
            u64 xp = pack2(xv, xv);
            const ulonglong2* wr = reinterpret_cast<const ulonglong2*>(&Wl[c*CH + fb]);
            #pragma unroll
            for (int r = 0; r < 4; r++) {
                ulonglong2 w = wr[r];
                acc2[2*r]   = fma2(xp, w.x, acc2[2*r]);
                acc2[2*r+1] = fma2(xp, w.y, acc2[2*r+1]);
            }
        }
        #pragma unroll
        for (int r = 0; r < 8; r++) {
            float lo, hi; unpack2(acc2[r], lo, hi);
            out[(b*CH + fb + 2*r    )*FLATN + v0 + vl] = lo;
            out[(b*CH + fb + 2*r + 1)*FLATN + v0 + vl] = hi;
        }
    } else {
        // ---- gumbel table path: one block per (b,i) sample row ----
        int bi = blockIdx.x - (GXIB + DENB);
        int b  = bi >> 8;
        int i  = bi & 255;
        uint32_t kb0, kb1;
        batch_keys(b, kb0, kb1);
        int n0 = t * 8;
        float g[8];
        #pragma unroll
        for (int r = 0; r < 8; r++)
            g[r] = gumbel_of(kb0, kb1, (uint32_t)(i*NPTS + n0 + r));
        float4* dst = reinterpret_cast<float4*>(&g_gum[bi*NPTS + n0]);
        dst[0] = make_float4(g[0], g[1], g[2], g[3]);
        dst[1] = make_float4(g[4], g[5], g[6], g[7]);
    }
}

// ---------------- sampling + gather + interleaved tf projection -------------
__global__ void __launch_bounds__(256) samplegather_kernel(const float* w_p1) {
    int bi = blockIdx.x;
    int b  = bi >> 8;
    int t  = threadIdx.x;

    float best = -3.402823466e38f;
    int   bidx = 0x7fffffff;
    {
        const float4* gv = reinterpret_cast<const float4*>(&g_gum[bi*NPTS]);
        const float4* lp = reinterpret_cast<const float4*>(&g_logp[b*NPTS]);
        int n0 = t * 8;
        #pragma unroll
        for (int r = 0; r < 2; r++) {
            float4 g = gv[t*2 + r];
            float4 l = lp[t*2 + r];
            float v0 = g.x + l.x, v1 = g.y + l.y, v2 = g.z + l.z, v3 = g.w + l.w;
            int nb = n0 + r*4;
            if (v0 > best) { best = v0; bidx = nb; }
            if (v1 > best) { best = v1; bidx = nb + 1; }
            if (v2 > best) { best = v2; bidx = nb + 2; }
            if (v3 > best) { best = v3; bidx = nb + 3; }
        }
    }
    __shared__ float sv[256];
    __shared__ int   si[256];
    __shared__ float ms[CH];
    __shared__ float tfs[CH];
    sv[t] = best; si[t] = bidx;
    __syncthreads();
    for (int s = 128; s > 0; s >>= 1) {
        if (t < s) {
            if (sv[t+s] > sv[t] || (sv[t+s] == sv[t] && si[t+s] < si[t])) {
                sv[t] = sv[t+s]; si[t] = si[t+s];
            }
        }
        __syncthreads();
    }
    int n = si[0];
    int src = (b*NPTS + n)*CH;
    if (t < CH) {
        ms[t]  = g_mpe[src + t];
        tfs[t] = g_xi[src + t];
    }
    __syncthreads();
    int i = bi & 255;
    if (t < CH) {
        const float* WI = g_Weff + CH*CH;        // rows [64:128)
        const float* WE = g_Weff + 2*CH*CH;      // rows [128:192)
        float accI = 0.f, accE = 0.f;
        #pragma unroll 8
        for (int j = 0; j < CH; j++) {
            float x = tfs[j];
            accI = fmaf(x, WI[j*CH + t], accI);
            accE = fmaf(x, WE[j*CH + t], accE);
        }
        g_tfP[(b*KSMP + i)*CH + t] = make_float2(accI, accE);
    } else if (t < CH + HID) {
        int j = t - CH;
        float d = 0.f;
        #pragma unroll
        for (int c = 0; c < CH; c++) d = fmaf(ms[c], w_p1[c*HID + j], d);
        g_B1T[(b*HID + j)*KSMP + i] = fmaf(d, g_s1[j], g_bias1[j]);
    } else if (t == 255) {
        g_nek[bi] = g_prob[b*NPTS + n];
    }
}

// ---------------- pairP: layers 1-3, 2 points/block, 3 blocks/SM target -----
__global__ void __launch_bounds__(256, 3) pairP_kernel(const float* w_p3, const float* b_p3) {
    __shared__ __align__(16) float  W2s[HID*HID];    // 4KB
    __shared__ float A1s[2][HID], b2s[HID], w3s[HID];
    __shared__ float bp3s;

    int blk = blockIdx.x;                            // 2048 blocks
    int b   = blk >> 10;
    int n0  = (blk & 1023) * 2;
    int bn  = b*NPTS + n0;
    int t   = threadIdx.x;                           // t = k

    for (int q = t; q < HID*HID; q += 256) W2s[q] = g_W2T[q];
    if (t < 2*HID) A1s[t >> 5][t & 31] = g_A1[bn*HID + t];
    if (t < HID) { b2s[t] = g_bias2[t]; w3s[t] = w_p3[t]; }
    if (t == 0) bp3s = b_p3[0];
    float ne = g_nek[b*KSMP + t];
    __syncthreads();

    // h1 for both points, packed in pairs; B1T column loaded once, used twice
    u64 h1a[HID/2], h1b[HID/2];
    #pragma unroll
    for (int i2 = 0; i2 < HID/2; i2++) {
        float blo = g_B1T[(b*HID + 2*i2    )*KSMP + t];
        float bhi = g_B1T[(b*HID + 2*i2 + 1)*KSMP + t];
        h1a[i2] = pack2(fmaxf(A1s[0][2*i2] + blo, 0.f), fmaxf(A1s[0][2*i2+1] + bhi, 0.f));
        h1b[i2] = pack2(fmaxf(A1s[1][2*i2] + blo, 0.f), fmaxf(A1s[1][2*i2+1] + bhi, 0.f));
    }

    // layer 2 (32x32, f32x2) + layer 3 (32->1); bias folded post-reduce,
    // unroll 2 to keep temp live-range small under the 3-blocks/SM reg cap
    float accA = 0.f, accB = 0.f;
    #pragma unroll 2
    for (int j = 0; j < HID; j++) {
        const ulonglong2* wp = reinterpret_cast<const ulonglong2*>(&W2s[j*HID]);
        u64 za = 0ULL, zb = 0ULL;
        #pragma unroll
        for (int q = 0; q < 8; q++) {
            ulonglong2 w = wp[q];                    // broadcast LDS.128
            za = fma2(h1a[2*q],     w.x, za);
            za = fma2(h1a[2*q + 1], w.y, za);
            zb = fma2(h1b[2*q],     w.x, zb);
            zb = fma2(h1b[2*q + 1], w.y, zb);
        }
        float l, h, b2 = b2s[j], w3 = w3s[j];
        unpack2(za, l, h); accA = fmaf(fmaxf(l + h + b2, 0.f), w3, accA);
        unpack2(zb, l, h); accB = fmaf(fmaxf(l + h + b2, 0.f), w3, accB);
    }
    float Pa = 1.f / (1.f + expf(-(accA + bp3s)));
    float Pb = 1.f / (1.f + expf(-(accB + bp3s)));
    g_wiwe[(bn    )*KSMP + t] = make_float2(Pa * ne, (1.f - Pa) * ne);
    g_wiwe[(bn + 1)*KSMP + t] = make_float2(Pb * ne, (1.f - Pb) * ne);
}

// ---------------- pairW: weighted sums over tfP, TW=8, MLP-8 pipelined ------
#define SWPAD 10                                 // u64 row pitch (16B-aligned rows)
__global__ void __launch_bounds__(256) pairW_kernel() {
    __shared__ __align__(16) u64 SB[KSMP*SWPAD]; // 20KB: wiweT -> partials
    __shared__ float2 sums[TW];
    int blk = blockIdx.x;                        // 512 blocks
    int b   = blk >> 8;                          // / (NPTS/TW)
    int n0  = (blk & 255) * TW;
    int bn  = b*NPTS + n0;
    int t   = threadIdx.x;

    // stage wiwe transposed: SB[kk*SWPAD + n] = wiwe[n][kk]
    const u64* wsrc = reinterpret_cast<const u64*>(g_wiwe + bn*KSMP);
    for (int idx = t; idx < TW*KSMP; idx += 256) {
        int n = idx >> 8, kk = idx & 255;
        SB[kk*SWPAD + n] = wsrc[n*KSMP + kk];
    }
    __syncthreads();

    // per-point scalar sums: warp w -> point w
    {
        int w = t >> 5, lane = t & 31;
        float si = 0.f, se = 0.f;
        #pragma unroll
        for (int kk = lane; kk < KSMP; kk += 32) {
            float x, y; unpack2(SB[kk*SWPAD + w], x, y);
            si += x; se += y;
        }
        si = warpsum(si); se = warpsum(se);
        if (lane == 0) sums[w] = make_float2(si, se);
    }

    // weighted sums: thread (c = t&63, quarter q = t>>6), MLP-8 batched LDG
    int c = t & 63, q = t >> 6;
    u64 acc[TW];
    #pragma unroll
    for (int n = 0; n < TW; n++) acc[n] = 0ULL;
    const u64* tfPb = reinterpret_cast<const u64*>(g_tfP + b*KSMP*CH) + c;
    #pragma unroll 1
    for (int kb = q*64; kb < q*64 + 64; kb += 8) {
        u64 t2[8];
        #pragma unroll
        for (int r = 0; r < 8; r++) t2[r] = tfPb[(kb + r)*CH];   // 8 LDG in flight
        #pragma unroll
        for (int r = 0; r < 8; r++) {
            const ulonglong2* wr =
                reinterpret_cast<const ulonglong2*>(&SB[(kb + r)*SWPAD]);
            ulonglong2 w0 = wr[0], w1 = wr[1], w2 = wr[2], w3 = wr[3];
            acc[0] = fma2(t2[r], w0.x, acc[0]);
            acc[1] = fma2(t2[r], w0.y, acc[1]);
            acc[2] = fma2(t2[r], w1.x, acc[2]);
            acc[3] = fma2(t2[r], w1.y, acc[3]);
            acc[4] = fma2(t2[r], w2.x, acc[4]);
            acc[5] = fma2(t2[r], w2.y, acc[5]);
            acc[6] = fma2(t2[r], w3.x, acc[6]);
            acc[7] = fma2(t2[r], w3.y, acc[7]);
        }
    }
    __syncthreads();                             // all SB reads done; reuse

    // partials: SB[n*256 + t] (conflict-free store & read)
    #pragma unroll
    for (int n = 0; n < TW; n++) SB[n*256 + t] = acc[n];
    __syncthreads();

    // finalize: combine quarters, normalize, write ctx
    for (int idx = t; idx < TW*CH; idx += 256) {
        int n = idx >> 6, cc = idx & 63;
        float si = 0.f, se = 0.f;
        #pragma unroll
        for (int qq = 0; qq < 4; qq++) {
            float x, y; unpack2(SB[n*256 + qq*64 + cc], x, y);
            si += x; se += y;
        }
        float2 s = sums[n];
        g_ctx[(bn + n)*CH + cc] = si / s.x + se / s.y;
    }
}

// ---------------- trivial scatter of projected ctx --------------------------
__global__ void __launch_bounds__(256) scatter_kernel(const int* mask_idx, float* out) {
    int idx = blockIdx.x * 256 + threadIdx.x;       // over BSZ*NPTS*CH
    int bn  = idx >> 6;
    int f   = idx & 63;
    int b   = bn >> 11;                              // / NPTS
    int v   = mask_idx[bn];
    out[(b*CH + f)*FLATN + v] += g_ctx[idx];
}

// -----------------------------------------------------------------------------
extern "C" void kernel_launch(void* const* d_in, const int* in_sizes, int n_in,
                              void* d_out, int out_size) {
    const float* input    = (const float*)d_in[0];
    const int*   mask_idx = (const int*)  d_in[1];
    const float* w_ne1 = (const float*)d_in[2];
    const float* b_ne1 = (const float*)d_in[3];
    const float* g_ne  = (const float*)d_in[4];
    const float* be_ne = (const float*)d_in[5];
    const float* w_ne2 = (const float*)d_in[6];
    const float* b_ne2 = (const float*)d_in[7];
    const float* w_p1  = (const float*)d_in[8];
    const float* b_p1  = (const float*)d_in[9];
    const float* g_p1  = (const float*)d_in[10];
    const float* be_p1 = (const float*)d_in[11];
    const float* w_p2  = (const float*)d_in[12];
    const float* b_p2  = (const float*)d_in[13];
    const float* g_p2  = (const float*)d_in[14];
    const float* be_p2 = (const float*)d_in[15];
    const float* w_p3  = (const float*)d_in[16];
    const float* b_p3  = (const float*)d_in[17];
    const float* w_r1  = (const float*)d_in[18];
    const float* b_r1  = (const float*)d_in[19];
    const float* w_r2  = (const float*)d_in[20];
    const float* b_r2  = (const float*)d_in[21];
    float* out = (float*)d_out;

    weffprep_kernel<<<4*CH, CH>>>(w_r1, w_r2, b_ne1, g_ne, be_ne,
                                  b_p1, g_p1, be_p1, w_p2, b_p2, g_p2, be_p2,
                                  b_r1, b_r2);
    gxidense_kernel<<<GXIB + DENB + GUMB, 256>>>(input, mask_idx, w_ne1, w_ne2,
                                                 b_ne2, w_p1, out);
    samplegather_kernel<<<BSZ*KSMP, 256>>>(w_p1);
    pairP_kernel<<<BSZ*NPTS/2, 256>>>(w_p3, b_p3);  // launch #4 -> ncu target
    pairW_kernel<<<BSZ*NPTS/TW, 256>>>();
    scatter_kernel<<<BSZ*NPTS*CH/256, 256>>>(mask_idx, out);
}

// round 16
// speedup vs baseline: 1.0726x; 1.0726x over previous
#include <cuda_runtime.h>
#include <stdint.h>

#define JAX_PARTITIONABLE 1

#define BSZ   2
#define CH    64
#define FLATN 16384
#define NPTS  2048
#define KSMP  256
#define HID   32
#define PT    8
#define TP    3                       // points per pairP block
#define NPB   683                     // ceil(NPTS/TP) blocks per batch
#define TW    8                       // points per pairW block
#define GXIB  (BSZ*NPTS/PT)          // 512 gxifeat blocks
#define DENB  (FLATN/64*BSZ)         // 512 dense blocks
#define GUMB  (BSZ*KSMP)             // 512 gumbel-table blocks

typedef unsigned long long u64;

// ---------------- device scratch ------------------------------------------
__device__ float g_xi    [BSZ*NPTS*CH];
__device__ float g_mpe   [BSZ*NPTS*CH];
__device__ float g_A1    [BSZ*NPTS*HID];
__device__ float g_prob  [BSZ*NPTS];
__device__ float g_logp  [BSZ*NPTS];
__device__ float g_B1T   [BSZ*HID*KSMP];     // [b][i][k], bias1 folded in
__device__ float2 g_tfP  [BSZ*KSMP*CH];      // interleaved {tf@W_I, tf@W_E}
__device__ float2 g_wiwe [BSZ*NPTS*KSMP];    // per-(n,k) {wi, we}
__device__ float g_nek   [BSZ*KSMP];
__device__ float g_gum   [BSZ*KSMP*NPTS];    // gumbel noise table [bi][n]
__device__ float g_ctx   [BSZ*NPTS*CH];      // projected ctx (dense, coalesced)
__device__ float g_Weff  [4*CH*CH];          // w_r1 @ w_r2
__device__ float g_beff  [CH];
__device__ float g_s1[HID], g_bias1[HID], g_W2T[HID*HID], g_bias2[HID];
__device__ float g_sne[HID], g_biasne[HID];

// ---------------- helpers ---------------------------------------------------
__device__ __forceinline__ float warpsum(float v) {
    #pragma unroll
    for (int o = 16; o > 0; o >>= 1) v += __shfl_xor_sync(0xffffffffu, v, o);
    return v;
}
__device__ __forceinline__ u64 pack2(float lo, float hi) {
    u64 r; asm("mov.b64 %0, {%1,%2};" : "=l"(r) : "f"(lo), "f"(hi)); return r;
}
__device__ __forceinline__ void unpack2(u64 v, float& lo, float& hi) {
    asm("mov.b64 {%0,%1}, %2;" : "=f"(lo), "=f"(hi) : "l"(v));
}
__device__ __forceinline__ u64 fma2(u64 a, u64 b, u64 c) {
    u64 d; asm("fma.rn.f32x2 %0, %1, %2, %3;" : "=l"(d) : "l"(a), "l"(b), "l"(c)); return d;
}
__device__ __forceinline__ uint32_t rotl32(uint32_t x, int d) {
    return (x << d) | (x >> (32 - d));
}
__device__ __forceinline__ void tf2x32(uint32_t k0, uint32_t k1,
                                       uint32_t x0, uint32_t x1,
                                       uint32_t& o0, uint32_t& o1) {
    uint32_t ks0 = k0, ks1 = k1, ks2 = k0 ^ k1 ^ 0x1BD11BDAu;
    x0 += ks0; x1 += ks1;
#define TF_RND(r) { x0 += x1; x1 = rotl32(x1, r); x1 ^= x0; }
    TF_RND(13) TF_RND(15) TF_RND(26) TF_RND(6)  x0 += ks1; x1 += ks2 + 1u;
    TF_RND(17) TF_RND(29) TF_RND(16) TF_RND(24) x0 += ks2; x1 += ks0 + 2u;
    TF_RND(13) TF_RND(15) TF_RND(26) TF_RND(6)  x0 += ks0; x1 += ks1 + 3u;
    TF_RND(17) TF_RND(29) TF_RND(16) TF_RND(24) x0 += ks1; x1 += ks2 + 4u;
    TF_RND(13) TF_RND(15) TF_RND(26) TF_RND(6)  x0 += ks2; x1 += ks0 + 5u;
#undef TF_RND
    o0 = x0; o1 = x1;
}
__device__ __forceinline__ void batch_keys(int b, uint32_t& kb0, uint32_t& kb1) {
#if JAX_PARTITIONABLE
    tf2x32(0u, 42u, 0u, (uint32_t)b, kb0, kb1);
#else
    uint32_t a0, a1, c0, c1;
    tf2x32(0u, 42u, 0u, 2u, a0, a1);
    tf2x32(0u, 42u, 1u, 3u, c0, c1);
    if (b == 0) { kb0 = a0; kb1 = c0; } else { kb0 = a1; kb1 = c1; }
#endif
}
__device__ __forceinline__ float gumbel_of(uint32_t kb0, uint32_t kb1, uint32_t m) {
    uint32_t o0, o1, bits;
#if JAX_PARTITIONABLE
    tf2x32(kb0, kb1, 0u, m, o0, o1);
    bits = o0 ^ o1;
#else
    const uint32_t half = (KSMP * NPTS) / 2;
    if (m < half) { tf2x32(kb0, kb1, m, m + half, o0, o1); bits = o0; }
    else          { tf2x32(kb0, kb1, m - half, m, o0, o1); bits = o1; }
#endif
    const float TINY = 1.1754943508222875e-38f;
    float f = __uint_as_float((bits >> 9) | 0x3f800000u) - 1.0f;
    float u = fmaxf(f + TINY, TINY);
    return -logf(-logf(u));
}

// ---------------- weff + prep (fused) ---------------------------------------
__global__ void weffprep_kernel(const float* w_r1, const float* w_r2,
                                const float* b_ne1, const float* g_ne, const float* be_ne,
                                const float* b_p1,  const float* g_p1, const float* be_p1,
                                const float* w_p2,  const float* b_p2, const float* g_p2,
                                const float* be_p2, const float* b_r1, const float* b_r2) {
    __shared__ float row[2*CH];
    int c = blockIdx.x, f = threadIdx.x;
    row[f]      = w_r1[c*2*CH + f];
    row[f + CH] = w_r1[c*2*CH + f + CH];
    __syncthreads();
    float acc = 0.f;
    #pragma unroll 8
    for (int m = 0; m < 2*CH; m++) acc = fmaf(row[m], w_r2[m*CH + f], acc);
    g_Weff[c*CH + f] = acc;

    if (blockIdx.x == 0) {
        int t = threadIdx.x;
        float inv = 1.0f / sqrtf(1.0f + 1e-5f);
        if (t < HID) {
            float sne = g_ne[t] * inv;
            g_sne[t] = sne;
            g_biasne[t] = fmaf(b_ne1[t], sne, be_ne[t]);
            float s1 = g_p1[t] * inv;
            g_s1[t] = s1;
            g_bias1[t] = fmaf(b_p1[t], s1, be_p1[t]);
            float s2 = g_p2[t] * inv;
            g_bias2[t] = fmaf(b_p2[t], s2, be_p2[t]);
            for (int i = 0; i < HID; i++)
                g_W2T[t*HID + i] = w_p2[i*HID + t] * s2;
        }
        if (t < CH) {
            float a2 = b_r2[t];
            for (int m = 0; m < 2*CH; m++) a2 = fmaf(b_r1[m], w_r2[m*CH + t], a2);
            g_beff[t] = a2;
        }
    }
}

// ---------------- fused gxifeat + dense + gumbel-table ----------------------
__global__ void __launch_bounds__(256) gxidense_kernel(
        const float* input, const int* mask_idx,
        const float* w_ne1, const float* w_ne2, const float* b_ne2,
        const float* w_p1, float* out) {
    __shared__ float X[CH*65];
    __shared__ __align__(16) float Wl[CH*CH];
    __shared__ float bl[CH];
    int t = threadIdx.x;

    if (blockIdx.x < GXIB) {
        // ---- gxifeat path ----
        float* xs = X;
        __shared__ int   vs[PT];
        __shared__ float divs[HID];
        int b  = blockIdx.x / (NPTS/PT);
        int p0 = (blockIdx.x % (NPTS/PT)) * PT;
        const float kc = -0.1439115683121279f;   // -ln(10000)/64
        if (t < PT) vs[t] = mask_idx[b*NPTS + p0 + t];
        if (t < HID) divs[t] = expf((float)(2*t) * kc);
        __syncthreads();
        for (int idx = t; idx < PT*CH; idx += 256) {
            int p = idx >> 6, c = idx & 63;
            int v = vs[p];
            float ang = (float)v * divs[c >> 1];
            float pe  = (c & 1) ? cosf(ang) : sinf(ang);
            float xi  = input[(b*CH + c)*FLATN + v] + pe;
            int bn = b*NPTS + p0 + p;
            g_xi [bn*CH + c] = xi;
            g_mpe[bn*CH + c] = pe;
            xs[p*CH + c] = xi;
        }
        __syncthreads();
        int w = t >> 5, j = t & 31;
        float dn = 0.f, dp = 0.f;
        #pragma unroll
        for (int c = 0; c < CH; c++) {
            float x = xs[w*CH + c];
            dn = fmaf(x, w_ne1[c*HID + j], dn);
            dp = fmaf(x, w_p1 [c*HID + j], dp);
        }
        int bn = b*NPTS + p0 + w;
        g_A1[bn*HID + j] = dp * g_s1[j];
        float h = fmaxf(fmaf(dn, g_sne[j], g_biasne[j]), 0.f);
        float s = warpsum(h * w_ne2[j]);
        if (j == 0) {
            float logit = s + b_ne2[0];
            float p = 1.f / (1.f + expf(-logit));
            g_prob[bn] = p;
            g_logp[bn] = logf(p);
        }
    } else if (blockIdx.x < GXIB + DENB) {
        // ---- dense path ----
        int d  = blockIdx.x - GXIB;
        int b  = d >> 8;
        int v0 = (d & 255) * 64;
        for (int q = t; q < CH*64; q += 256) {
            int c = q >> 6, vl = q & 63;
            X[c*65 + vl] = input[(b*CH + c)*FLATN + v0 + vl];
        }
        for (int q = t; q < CH*CH; q += 256) Wl[q] = g_Weff[q] + g_Weff[3*CH*CH + q];
        if (t < CH) bl[t] = g_beff[t];
        __syncthreads();

        int vl = t & 63, fb = (t >> 6) * 16;
        u64 acc2[8];
        #pragma unroll
        for (int r = 0; r < 8; r++) acc2[r] = pack2(bl[fb + 2*r], bl[fb + 2*r + 1]);
        for (int c = 0; c < CH; c++) {
            float xv = X[c*65 + vl];
            u64 xp = pack2(xv, xv);
            const ulonglong2* wr = reinterpret_cast<const ulonglong2*>(&Wl[c*CH + fb]);
            #pragma unroll
            for (int r = 0; r < 4; r++) {
                ulonglong2 w = wr[r];
                acc2[2*r]   = fma2(xp, w.x, acc2[2*r]);
                acc2[2*r+1] = fma2(xp, w.y, acc2[2*r+1]);
            }
        }
        #pragma unroll
        for (int r = 0; r < 8; r++) {
            float lo, hi; unpack2(acc2[r], lo, hi);
            out[(b*CH + fb + 2*r    )*FLATN + v0 + vl] = lo;
            out[(b*CH + fb + 2*r + 1)*FLATN + v0 + vl] = hi;
        }
    } else {
        // ---- gumbel table path: one block per (b,i) sample row ----
        int bi = blockIdx.x - (GXIB + DENB);
        int b  = bi >> 8;
        int i  = bi & 255;
        uint32_t kb0, kb1;
        batch_keys(b, kb0, kb1);
        int n0 = t * 8;
        float g[8];
        #pragma unroll
        for (int r = 0; r < 8; r++)
            g[r] = gumbel_of(kb0, kb1, (uint32_t)(i*NPTS + n0 + r));
        float4* dst = reinterpret_cast<float4*>(&g_gum[bi*NPTS + n0]);
        dst[0] = make_float4(g[0], g[1], g[2], g[3]);
        dst[1] = make_float4(g[4], g[5], g[6], g[7]);
    }
}

// ---------------- sampling + gather + interleaved tf projection -------------
__global__ void __launch_bounds__(256) samplegather_kernel(const float* w_p1) {
    int bi = blockIdx.x;
    int b  = bi >> 8;
    int t  = threadIdx.x;

    float best = -3.402823466e38f;
    int   bidx = 0x7fffffff;
    {
        const float4* gv = reinterpret_cast<const float4*>(&g_gum[bi*NPTS]);
        const float4* lp = reinterpret_cast<const float4*>(&g_logp[b*NPTS]);
        int n0 = t * 8;
        #pragma unroll
        for (int r = 0; r < 2; r++) {
            float4 g = gv[t*2 + r];
            float4 l = lp[t*2 + r];
            float v0 = g.x + l.x, v1 = g.y + l.y, v2 = g.z + l.z, v3 = g.w + l.w;
            int nb = n0 + r*4;
            if (v0 > best) { best = v0; bidx = nb; }
            if (v1 > best) { best = v1; bidx = nb + 1; }
            if (v2 > best) { best = v2; bidx = nb + 2; }
            if (v3 > best) { best = v3; bidx = nb + 3; }
        }
    }
    __shared__ float sv[256];
    __shared__ int   si[256];
    __shared__ float ms[CH];
    __shared__ float tfs[CH];
    sv[t] = best; si[t] = bidx;
    __syncthreads();
    for (int s = 128; s > 0; s >>= 1) {
        if (t < s) {
            if (sv[t+s] > sv[t] || (sv[t+s] == sv[t] && si[t+s] < si[t])) {
                sv[t] = sv[t+s]; si[t] = si[t+s];
            }
        }
        __syncthreads();
    }
    int n = si[0];
    int src = (b*NPTS + n)*CH;
    if (t < CH) {
        ms[t]  = g_mpe[src + t];
        tfs[t] = g_xi[src + t];
    }
    __syncthreads();
    int i = bi & 255;
    if (t < CH) {
        const float* WI = g_Weff + CH*CH;        // rows [64:128)
        const float* WE = g_Weff + 2*CH*CH;      // rows [128:192)
        float accI = 0.f, accE = 0.f;
        #pragma unroll 8
        for (int j = 0; j < CH; j++) {
            float x = tfs[j];
            accI = fmaf(x, WI[j*CH + t], accI);
            accE = fmaf(x, WE[j*CH + t], accE);
        }
        g_tfP[(b*KSMP + i)*CH + t] = make_float2(accI, accE);
    } else if (t < CH + HID) {
        int j = t - CH;
        float d = 0.f;
        #pragma unroll
        for (int c = 0; c < CH; c++) d = fmaf(ms[c], w_p1[c*HID + j], d);
        g_B1T[(b*HID + j)*KSMP + i] = fmaf(d, g_s1[j], g_bias1[j]);
    } else if (t == 255) {
        g_nek[bi] = g_prob[b*NPTS + n];
    }
}

// ---------------- pairP: layers 1-3, 3 points/block -------------------------
__global__ void __launch_bounds__(256) pairP_kernel(const float* w_p3, const float* b_p3) {
    __shared__ __align__(16) float  W2s[HID*HID];    // 4KB
    __shared__ float A1s[TP][HID], b2s[HID], w3s[HID];
    __shared__ float bp3s;

    int blk = blockIdx.x;                            // BSZ*NPB blocks
    int b   = blk / NPB;
    int n0  = (blk % NPB) * TP;
    int t   = threadIdx.x;                           // t = k

    for (int q = t; q < HID*HID; q += 256) W2s[q] = g_W2T[q];
    if (t < TP*HID) {
        int p = t >> 5;
        int nn = n0 + p; if (nn >= NPTS) nn = NPTS - 1;  // clamp overhang
        A1s[p][t & 31] = g_A1[(b*NPTS + nn)*HID + (t & 31)];
    }
    if (t < HID) { b2s[t] = g_bias2[t]; w3s[t] = w_p3[t]; }
    if (t == 0) bp3s = b_p3[0];
    float ne = g_nek[b*KSMP + t];
    __syncthreads();

    // h1 for all TP points; B1T column loaded once, reused TP times
    u64 h1[TP][HID/2];
    #pragma unroll
    for (int i2 = 0; i2 < HID/2; i2++) {
        float blo = g_B1T[(b*HID + 2*i2    )*KSMP + t];
        float bhi = g_B1T[(b*HID + 2*i2 + 1)*KSMP + t];
        #pragma unroll
        for (int p = 0; p < TP; p++)
            h1[p][i2] = pack2(fmaxf(A1s[p][2*i2] + blo, 0.f),
                              fmaxf(A1s[p][2*i2+1] + bhi, 0.f));
    }

    // layer 2 (32x32, f32x2) + layer 3 (32->1); each W LDS.128 feeds 2*TP fma2
    float acc[TP];
    #pragma unroll
    for (int p = 0; p < TP; p++) acc[p] = 0.f;
    #pragma unroll 2
    for (int j = 0; j < HID; j++) {
        const ulonglong2* wp = reinterpret_cast<const ulonglong2*>(&W2s[j*HID]);
        u64 z[TP];
        #pragma unroll
        for (int p = 0; p < TP; p++) z[p] = 0ULL;
        #pragma unroll
        for (int q = 0; q < 8; q++) {
            ulonglong2 w = wp[q];                    // broadcast LDS.128
            #pragma unroll
            for (int p = 0; p < TP; p++) {
                z[p] = fma2(h1[p][2*q],     w.x, z[p]);
                z[p] = fma2(h1[p][2*q + 1], w.y, z[p]);
            }
        }
        float b2 = b2s[j], w3 = w3s[j];
        #pragma unroll
        for (int p = 0; p < TP; p++) {
            float l, h; unpack2(z[p], l, h);
            acc[p] = fmaf(fmaxf(l + h + b2, 0.f), w3, acc[p]);
        }
    }
    #pragma unroll
    for (int p = 0; p < TP; p++) {
        int nn = n0 + p;
        if (nn < NPTS) {
            float P = 1.f / (1.f + expf(-(acc[p] + bp3s)));
            g_wiwe[(b*NPTS + nn)*KSMP + t] = make_float2(P * ne, (1.f - P) * ne);
        }
    }
}

// ---------------- pairW: weighted sums over tfP, TW=8, MLP-8 pipelined ------
#define SWPAD 10                                 // u64 row pitch (16B-aligned rows)
__global__ void __launch_bounds__(256) pairW_kernel() {
    __shared__ __align__(16) u64 SB[KSMP*SWPAD]; // 20KB: wiweT -> partials
    __shared__ float2 sums[TW];
    int blk = blockIdx.x;                        // 512 blocks
    int b   = blk >> 8;                          // / (NPTS/TW)
    int n0  = (blk & 255) * TW;
    int bn  = b*NPTS + n0;
    int t   = threadIdx.x;

    // stage wiwe transposed: SB[kk*SWPAD + n] = wiwe[n][kk]
    const u64* wsrc = reinterpret_cast<const u64*>(g_wiwe + bn*KSMP);
    for (int idx = t; idx < TW*KSMP; idx += 256) {
        int n = idx >> 8, kk = idx & 255;
        SB[kk*SWPAD + n] = wsrc[n*KSMP + kk];
    }
    __syncthreads();

    // per-point scalar sums: warp w -> point w
    {
        int w = t >> 5, lane = t & 31;
        float si = 0.f, se = 0.f;
        #pragma unroll
        for (int kk = lane; kk < KSMP; kk += 32) {
            float x, y; unpack2(SB[kk*SWPAD + w], x, y);
            si += x; se += y;
        }
        si = warpsum(si); se = warpsum(se);
        if (lane == 0) sums[w] = make_float2(si, se);
    }

    // weighted sums: thread (c = t&63, quarter q = t>>6), MLP-8 batched LDG
    int c = t & 63, q = t >> 6;
    u64 acc[TW];
    #pragma unroll
    for (int n = 0; n < TW; n++) acc[n] = 0ULL;
    const u64* tfPb = reinterpret_cast<const u64*>(g_tfP + b*KSMP*CH) + c;
    #pragma unroll 1
    for (int kb = q*64; kb < q*64 + 64; kb += 8) {
        u64 t2[8];
        #pragma unroll
        for (int r = 0; r < 8; r++) t2[r] = tfPb[(kb + r)*CH];   // 8 LDG in flight
        #pragma unroll
        for (int r = 0; r < 8; r++) {
            const ulonglong2* wr =
                reinterpret_cast<const ulonglong2*>(&SB[(kb + r)*SWPAD]);
            ulonglong2 w0 = wr[0], w1 = wr[1], w2 = wr[2], w3 = wr[3];
            acc[0] = fma2(t2[r], w0.x, acc[0]);
            acc[1] = fma2(t2[r], w0.y, acc[1]);
            acc[2] = fma2(t2[r], w1.x, acc[2]);
            acc[3] = fma2(t2[r], w1.y, acc[3]);
            acc[4] = fma2(t2[r], w2.x, acc[4]);
            acc[5] = fma2(t2[r], w2.y, acc[5]);
            acc[6] = fma2(t2[r], w3.x, acc[6]);
            acc[7] = fma2(t2[r], w3.y, acc[7]);
        }
    }
    __syncthreads();                             // all SB reads done; reuse

    // partials: SB[n*256 + t] (conflict-free store & read)
    #pragma unroll
    for (int n = 0; n < TW; n++) SB[n*256 + t] = acc[n];
    __syncthreads();

    // finalize: combine quarters, normalize, write ctx
    for (int idx = t; idx < TW*CH; idx += 256) {
        int n = idx >> 6, cc = idx & 63;
        float si = 0.f, se = 0.f;
        #pragma unroll
        for (int qq = 0; qq < 4; qq++) {
            float x, y; unpack2(SB[n*256 + qq*64 + cc], x, y);
            si += x; se += y;
        }
        float2 s = sums[n];
        g_ctx[(bn + n)*CH + cc] = si / s.x + se / s.y;
    }
}

// ---------------- trivial scatter of projected ctx --------------------------
__global__ void __launch_bounds__(256) scatter_kernel(const int* mask_idx, float* out) {
    int idx = blockIdx.x * 256 + threadIdx.x;       // over BSZ*NPTS*CH
    int bn  = idx >> 6;
    int f   = idx & 63;
    int b   = bn >> 11;                              // / NPTS
    int v   = mask_idx[bn];
    out[(b*CH + f)*FLATN + v] += g_ctx[idx];
}

// -----------------------------------------------------------------------------
extern "C" void kernel_launch(void* const* d_in, const int* in_sizes, int n_in,
                              void* d_out, int out_size) {
    const float* input    = (const float*)d_in[0];
    const int*   mask_idx = (const int*)  d_in[1];
    const float* w_ne1 = (const float*)d_in[2];
    const float* b_ne1 = (const float*)d_in[3];
    const float* g_ne  = (const float*)d_in[4];
    const float* be_ne = (const float*)d_in[5];
    const float* w_ne2 = (const float*)d_in[6];
    const float* b_ne2 = (const float*)d_in[7];
    const float* w_p1  = (const float*)d_in[8];
    const float* b_p1  = (const float*)d_in[9];
    const float* g_p1  = (const float*)d_in[10];
    const float* be_p1 = (const float*)d_in[11];
    const float* w_p2  = (const float*)d_in[12];
    const float* b_p2  = (const float*)d_in[13];
    const float* g_p2  = (const float*)d_in[14];
    const float* be_p2 = (const float*)d_in[15];
    const float* w_p3  = (const float*)d_in[16];
    const float* b_p3  = (const float*)d_in[17];
    const float* w_r1  = (const float*)d_in[18];
    const float* b_r1  = (const float*)d_in[19];
    const float* w_r2  = (const float*)d_in[20];
    const float* b_r2  = (const float*)d_in[21];
    float* out = (float*)d_out;

    weffprep_kernel<<<4*CH, CH>>>(w_r1, w_r2, b_ne1, g_ne, be_ne,
                                  b_p1, g_p1, be_p1, w_p2, b_p2, g_p2, be_p2,
                                  b_r1, b_r2);
    gxidense_kernel<<<GXIB + DENB + GUMB, 256>>>(input, mask_idx, w_ne1, w_ne2,
                                                 b_ne2, w_p1, out);
    samplegather_kernel<<<BSZ*KSMP, 256>>>(w_p1);
    pairP_kernel<<<BSZ*NPB, 256>>>(w_p3, b_p3);     // launch #4 -> ncu target
    pairW_kernel<<<BSZ*NPTS/TW, 256>>>();
    scatter_kernel<<<BSZ*NPTS*CH/256, 256>>>(mask_idx, out);
}